// round 1
// baseline (speedup 1.0000x reference)
#include <cuda_runtime.h>
#include <math.h>

#define N_NODES 50000
#define N_EDGES 600000
#define D 128
#define N_RELS 460

// ---------------- device scratch (static, no allocation) ----------------
__device__ float g_u[3 * D];            // collapsed attention vector
__device__ float g_s_src[N_NODES];      // dot(h[n], u_s)
__device__ float g_s_dst[N_NODES];      // dot(h[n], u_t)
__device__ float g_s_rel[N_RELS];       // dot(emb_rel[r], u_r)
__device__ int   g_deg[N_NODES];
__device__ int   g_off[N_NODES + 1];
__device__ int   g_cursor[N_NODES];
__device__ float g_e_sorted[N_EDGES];   // edge scores grouped by dst
__device__ int   g_src_sorted[N_EDGES]; // matching src ids

// ---------------- K0: zero counters ----------------
__global__ void k_zero() {
    int i = blockIdx.x * blockDim.x + threadIdx.x;
    if (i < N_NODES) { g_deg[i] = 0; g_cursor[i] = 0; }
}

// ---------------- K1: u = attn_fc_w.T @ attn_fc2_w ----------------
// attn_fc_w: [D, 3D] row-major (out, in); attn_fc2_w: [1, D]
__global__ void k_compute_u(const float* __restrict__ W, const float* __restrict__ w2) {
    int i = blockIdx.x * blockDim.x + threadIdx.x;
    if (i < 3 * D) {
        float s = 0.f;
        #pragma unroll 4
        for (int o = 0; o < D; o++) s += w2[o] * W[o * (3 * D) + i];
        g_u[i] = s;
    }
}

// ---------------- K2: per-node / per-rel scalar scores ----------------
// one warp per node (or rel)
__global__ void k_scores(const float* __restrict__ h, const float* __restrict__ emb_rel) {
    int lane = threadIdx.x & 31;
    int gw = blockIdx.x * (blockDim.x >> 5) + (threadIdx.x >> 5);
    if (gw < N_NODES) {
        float4 hv = ((const float4*)h)[gw * 32 + lane];
        float4 u0 = ((const float4*)g_u)[lane];
        float4 u1 = ((const float4*)g_u)[32 + lane];
        float ss = hv.x * u0.x + hv.y * u0.y + hv.z * u0.z + hv.w * u0.w;
        float sd = hv.x * u1.x + hv.y * u1.y + hv.z * u1.z + hv.w * u1.w;
        #pragma unroll
        for (int o = 16; o; o >>= 1) {
            ss += __shfl_xor_sync(0xffffffffu, ss, o);
            sd += __shfl_xor_sync(0xffffffffu, sd, o);
        }
        if (lane == 0) { g_s_src[gw] = ss; g_s_dst[gw] = sd; }
    } else if (gw < N_NODES + N_RELS) {
        int r = gw - N_NODES;
        float4 rv = ((const float4*)emb_rel)[r * 32 + lane];
        float4 u2 = ((const float4*)g_u)[64 + lane];
        float sr = rv.x * u2.x + rv.y * u2.y + rv.z * u2.z + rv.w * u2.w;
        #pragma unroll
        for (int o = 16; o; o >>= 1) sr += __shfl_xor_sync(0xffffffffu, sr, o);
        if (lane == 0) g_s_rel[r] = sr;
    }
}

// ---------------- K3: count in-degree per dst ----------------
__global__ void k_count(const int* __restrict__ edst) {
    int i = blockIdx.x * blockDim.x + threadIdx.x;
    if (i < N_EDGES) atomicAdd(&g_deg[edst[i]], 1);
}

// ---------------- K4: single-block exclusive scan of deg -> off ----------------
__global__ void k_scan() {
    __shared__ int sm[1024];
    const int T = 1024;
    const int C = (N_NODES + T - 1) / T;  // 49
    int t = threadIdx.x;
    int base = t * C;
    int s = 0;
    for (int i = 0; i < C; i++) {
        int idx = base + i;
        if (idx < N_NODES) s += g_deg[idx];
    }
    sm[t] = s;
    __syncthreads();
    for (int off = 1; off < T; off <<= 1) {
        int v = (t >= off) ? sm[t - off] : 0;
        __syncthreads();
        sm[t] += v;
        __syncthreads();
    }
    int pre = sm[t] - s;  // exclusive prefix of this thread's chunk
    for (int i = 0; i < C; i++) {
        int idx = base + i;
        if (idx < N_NODES) {
            int d = g_deg[idx];
            g_off[idx] = pre;
            pre += d;
        }
    }
    if (t == T - 1) g_off[N_NODES] = sm[T - 1];  // = N_EDGES
}

// ---------------- K5: compute edge score, scatter into CSR slots ----------------
__global__ void k_fill(const int* __restrict__ esrc, const int* __restrict__ edst,
                       const int* __restrict__ etype) {
    int i = blockIdx.x * blockDim.x + threadIdx.x;
    if (i >= N_EDGES) return;
    int s = esrc[i], d = edst[i], r = etype[i];
    float e = g_s_src[s] + g_s_dst[d] + g_s_rel[r];
    e = (e >= 0.f) ? e : 0.01f * e;  // leaky_relu slope 0.01
    int pos = g_off[d] + atomicAdd(&g_cursor[d], 1);
    g_e_sorted[pos] = e;
    g_src_sorted[pos] = s;
}

// ---------------- K6: self-loop GEMM  out = h @ loop_weight ----------------
// block = 256 threads: tx=tid&31 -> column quad [4tx,4tx+4), ty=tid>>5 -> 4 rows
// each block handles 32 rows.
__global__ void k_gemm(const float* __restrict__ h, const float* __restrict__ W,
                       float* __restrict__ out) {
    __shared__ float hsT[128][36];  // [k][row], padded; 4-row groups 16B-aligned
    int row0 = blockIdx.x * 32;
    int tid = threadIdx.x;
    for (int idx = tid; idx < 32 * 128; idx += 256) {
        int r = idx >> 7, k = idx & 127;
        int row = row0 + r;
        hsT[k][r] = (row < N_NODES) ? h[row * D + k] : 0.f;
    }
    __syncthreads();
    int tx = tid & 31, ty = tid >> 5;
    float4 acc0 = {0, 0, 0, 0}, acc1 = {0, 0, 0, 0}, acc2 = {0, 0, 0, 0}, acc3 = {0, 0, 0, 0};
    #pragma unroll 8
    for (int k = 0; k < 128; k++) {
        float4 wv = ((const float4*)W)[k * 32 + tx];
        float4 hv = *((const float4*)&hsT[k][ty * 4]);
        acc0.x += hv.x * wv.x; acc0.y += hv.x * wv.y; acc0.z += hv.x * wv.z; acc0.w += hv.x * wv.w;
        acc1.x += hv.y * wv.x; acc1.y += hv.y * wv.y; acc1.z += hv.y * wv.z; acc1.w += hv.y * wv.w;
        acc2.x += hv.z * wv.x; acc2.y += hv.z * wv.y; acc2.z += hv.z * wv.z; acc2.w += hv.z * wv.w;
        acc3.x += hv.w * wv.x; acc3.y += hv.w * wv.y; acc3.z += hv.w * wv.z; acc3.w += hv.w * wv.w;
    }
    int rbase = row0 + ty * 4;
    if (rbase + 0 < N_NODES) ((float4*)out)[(rbase + 0) * 32 + tx] = acc0;
    if (rbase + 1 < N_NODES) ((float4*)out)[(rbase + 1) * 32 + tx] = acc1;
    if (rbase + 2 < N_NODES) ((float4*)out)[(rbase + 2) * 32 + tx] = acc2;
    if (rbase + 3 < N_NODES) ((float4*)out)[(rbase + 3) * 32 + tx] = acc3;
}

// ---------------- K7: per-dst softmax + weighted gather-sum ----------------
// one warp per destination node; out already holds self-loop term.
__global__ void k_aggregate(const float* __restrict__ h, float* __restrict__ out) {
    int lane = threadIdx.x & 31;
    int n = blockIdx.x * (blockDim.x >> 5) + (threadIdx.x >> 5);
    if (n >= N_NODES) return;
    int beg = g_off[n], end = g_off[n + 1];
    if (beg == end) return;

    // pass 1: exact segment max
    float m = -3.4e38f;
    for (int j = beg + lane; j < end; j += 32) m = fmaxf(m, g_e_sorted[j]);
    #pragma unroll
    for (int o = 16; o; o >>= 1) m = fmaxf(m, __shfl_xor_sync(0xffffffffu, m, o));

    // pass 2: accumulate sum(exp) and sum(exp * h[src])
    float4 acc = {0, 0, 0, 0};
    float den = 0.f;
    for (int j = beg; j < end; j++) {
        float ex = __expf(g_e_sorted[j] - m);  // lane-uniform
        den += ex;
        int src = g_src_sorted[j];
        float4 hv = ((const float4*)h)[src * 32 + lane];
        acc.x += ex * hv.x; acc.y += ex * hv.y; acc.z += ex * hv.z; acc.w += ex * hv.w;
    }
    float inv = 1.f / den;
    float4* op = (float4*)out + n * 32 + lane;
    float4 o = *op;
    o.x += acc.x * inv; o.y += acc.y * inv; o.z += acc.z * inv; o.w += acc.w * inv;
    *op = o;
}

// ---------------- launch ----------------
extern "C" void kernel_launch(void* const* d_in, const int* in_sizes, int n_in,
                              void* d_out, int out_size) {
    const float* h          = (const float*)d_in[0];
    const float* emb_rel    = (const float*)d_in[1];
    const float* attn_fc_w  = (const float*)d_in[2];
    const float* attn_fc2_w = (const float*)d_in[3];
    const float* loop_w     = (const float*)d_in[4];
    const int*   esrc       = (const int*)d_in[5];
    const int*   edst       = (const int*)d_in[6];
    const int*   etype      = (const int*)d_in[7];
    float* out = (float*)d_out;

    k_zero<<<(N_NODES + 255) / 256, 256>>>();
    k_compute_u<<<3, 128>>>(attn_fc_w, attn_fc2_w);
    k_scores<<<(N_NODES + N_RELS + 7) / 8, 256>>>(h, emb_rel);
    k_count<<<(N_EDGES + 255) / 256, 256>>>(edst);
    k_scan<<<1, 1024>>>();
    k_fill<<<(N_EDGES + 255) / 256, 256>>>(esrc, edst, etype);
    k_gemm<<<(N_NODES + 31) / 32, 256>>>(h, loop_w, out);
    k_aggregate<<<(N_NODES + 7) / 8, 256>>>(h, out);
}

// round 2
// speedup vs baseline: 1.1775x; 1.1775x over previous
#include <cuda_runtime.h>
#include <math.h>

#define N_NODES 50000
#define N_EDGES 600000
#define D 128
#define N_RELS 460

#define DEG_PAD 53248               // 1024 threads * 52 (multiple of 4)
#define SCORE_BLOCKS 198            // ceil((N_NODES+N_RELS)/256)
#define COUNT_BLOCKS 586            // ceil(N_EDGES/1024), 4 edges/thread

// ---------------- device scratch (static, zero-init; invariants keep it clean) ----------------
__device__ int   g_deg[DEG_PAD];        // zeroed at init; count fills, fill's atomicSub drains back to 0
__device__ int   g_off[N_NODES + 1];
__device__ float g_s_src[N_NODES];
__device__ float g_s_dst[N_NODES];
__device__ float g_s_rel[N_RELS];
__device__ float g_ex_sorted[N_EDGES];  // exp(edge score), grouped by dst
__device__ int   g_src_sorted[N_EDGES];

// ---------------- f32x2 packed-FMA helpers ----------------
#define PACK2(d, f)        asm("mov.b64 %0, {%1, %1};" : "=l"(d) : "f"(f))
#define FMA2(d, a, b)      asm("fma.rn.f32x2 %0, %1, %2, %0;" : "+l"(d) : "l"(a), "l"(b))
#define UNPACK2(lo, hi, p) asm("mov.b64 {%0, %1}, %2;" : "=f"(lo), "=f"(hi) : "l"(p))

// ============================================================================
// K1: fused scores + degree count.
//   blocks [0, SCORE_BLOCKS): compute u = attn_fc_w.T @ attn_fc2_w per block
//     (redundant, cheap), then per-node/per-rel scalar scores.
//   blocks [SCORE_BLOCKS, ...): in-degree histogram (4 edges/thread, int4).
// ============================================================================
__global__ void k_scores_count(const float* __restrict__ h,
                               const float* __restrict__ emb_rel,
                               const float* __restrict__ W,
                               const float* __restrict__ w2,
                               const int*   __restrict__ edst) {
    if (blockIdx.x < SCORE_BLOCKS) {
        __shared__ float su[3 * D];
        int t = threadIdx.x;
        // ---- phase 1: u[384] ----
        {
            float s1 = 0.f, s2 = 0.f;
            #pragma unroll 4
            for (int o = 0; o < D; o++) {
                float c = w2[o];
                s1 += c * W[o * (3 * D) + t];
                if (t < 128) s2 += c * W[o * (3 * D) + t + 256];
            }
            su[t] = s1;
            if (t < 128) su[t + 256] = s2;
        }
        __syncthreads();
        // ---- phase 2: each warp handles 32 units ----
        int lane = t & 31;
        int wid  = t >> 5;
        float4 u0 = ((const float4*)su)[lane];        // u_s
        float4 u1 = ((const float4*)su)[32 + lane];   // u_t
        float4 u2 = ((const float4*)su)[64 + lane];   // u_r
        int base = (blockIdx.x * 8 + wid) * 32;
        #pragma unroll 4
        for (int i = 0; i < 32; i++) {
            int gw = base + i;
            if (gw < N_NODES) {
                float4 hv = ((const float4*)h)[gw * 32 + lane];
                float ss = hv.x * u0.x + hv.y * u0.y + hv.z * u0.z + hv.w * u0.w;
                float sd = hv.x * u1.x + hv.y * u1.y + hv.z * u1.z + hv.w * u1.w;
                #pragma unroll
                for (int o = 16; o; o >>= 1) {
                    ss += __shfl_xor_sync(0xffffffffu, ss, o);
                    sd += __shfl_xor_sync(0xffffffffu, sd, o);
                }
                if (lane == 0) { g_s_src[gw] = ss; g_s_dst[gw] = sd; }
            } else if (gw < N_NODES + N_RELS) {
                int r = gw - N_NODES;
                float4 rv = ((const float4*)emb_rel)[r * 32 + lane];
                float sr = rv.x * u2.x + rv.y * u2.y + rv.z * u2.z + rv.w * u2.w;
                #pragma unroll
                for (int o = 16; o; o >>= 1) sr += __shfl_xor_sync(0xffffffffu, sr, o);
                if (lane == 0) g_s_rel[r] = sr;
            }
        }
    } else {
        // ---- degree count: 4 edges per thread ----
        int i4 = (blockIdx.x - SCORE_BLOCKS) * 256 + threadIdx.x;
        if (i4 * 4 < N_EDGES) {
            int4 d4 = ((const int4*)edst)[i4];
            atomicAdd(&g_deg[d4.x], 1);
            atomicAdd(&g_deg[d4.y], 1);
            atomicAdd(&g_deg[d4.z], 1);
            atomicAdd(&g_deg[d4.w], 1);
        }
    }
}

// ============================================================================
// K2: single-block exclusive scan (int4-vectorized over zero-padded deg)
// ============================================================================
__global__ void k_scan() {
    __shared__ int sm[1024];
    int t = threadIdx.x;
    int4 buf[13];
    int s = 0;
    #pragma unroll
    for (int i = 0; i < 13; i++) {
        buf[i] = ((const int4*)g_deg)[t * 13 + i];
        s += buf[i].x + buf[i].y + buf[i].z + buf[i].w;
    }
    sm[t] = s;
    __syncthreads();
    for (int off = 1; off < 1024; off <<= 1) {
        int v = (t >= off) ? sm[t - off] : 0;
        __syncthreads();
        sm[t] += v;
        __syncthreads();
    }
    int pre = sm[t] - s;  // exclusive prefix of this thread's chunk
    int base = t * 52;
    #pragma unroll
    for (int i = 0; i < 13; i++) {
        int idx = base + i * 4;
        if (idx + 3 <= N_NODES) {
            g_off[idx]     = pre;                 pre += buf[i].x;
            g_off[idx + 1] = pre;                 pre += buf[i].y;
            g_off[idx + 2] = pre;                 pre += buf[i].z;
            g_off[idx + 3] = pre;                 pre += buf[i].w;
        } else {
            if (idx     <= N_NODES) g_off[idx]     = pre;  pre += buf[i].x;
            if (idx + 1 <= N_NODES) g_off[idx + 1] = pre;  pre += buf[i].y;
            if (idx + 2 <= N_NODES) g_off[idx + 2] = pre;  pre += buf[i].z;
            if (idx + 3 <= N_NODES) g_off[idx + 3] = pre;  pre += buf[i].w;
        }
    }
}

// ============================================================================
// K3: edge score -> exp, scatter into CSR slots.
//   atomicSub drains g_deg back to 0 (keeps counters clean across graph replays)
// ============================================================================
__global__ void k_fill(const int* __restrict__ esrc, const int* __restrict__ edst,
                       const int* __restrict__ etype) {
    int i4 = blockIdx.x * 256 + threadIdx.x;
    if (i4 * 4 >= N_EDGES) return;
    int4 s4 = ((const int4*)esrc)[i4];
    int4 d4 = ((const int4*)edst)[i4];
    int4 t4 = ((const int4*)etype)[i4];
    #pragma unroll
    for (int j = 0; j < 4; j++) {
        int s = (j == 0) ? s4.x : (j == 1) ? s4.y : (j == 2) ? s4.z : s4.w;
        int d = (j == 0) ? d4.x : (j == 1) ? d4.y : (j == 2) ? d4.z : d4.w;
        int r = (j == 0) ? t4.x : (j == 1) ? t4.y : (j == 2) ? t4.z : t4.w;
        float e = g_s_src[s] + g_s_dst[d] + g_s_rel[r];
        e = (e >= 0.f) ? e : 0.01f * e;                 // leaky_relu, slope 0.01
        int pos = g_off[d] + (atomicSub(&g_deg[d], 1) - 1);
        g_ex_sorted[pos]  = __expf(e);                  // softmax is shift-invariant; e bounded ~|3|
        g_src_sorted[pos] = s;
    }
}

// ============================================================================
// K4: self-loop GEMM  out = h @ loop_weight   (packed f32x2 FMA)
//   block 256 thr, tile 64 rows x 128 cols; thread: 8 rows (4 row-pairs) x 4 cols
// ============================================================================
__global__ void __launch_bounds__(256) k_gemm(const float* __restrict__ h,
                                              const float* __restrict__ W,
                                              float* __restrict__ out) {
    __shared__ float hsT[128][68];   // [k][row]; stride 272B (16B-aligned for LDS.128)
    int row0 = blockIdx.x * 64;
    int tid = threadIdx.x;
    for (int idx = tid; idx < 64 * 128; idx += 256) {
        int r = idx >> 7, k = idx & 127;
        int row = row0 + r;
        hsT[k][r] = (row < N_NODES) ? h[row * D + k] : 0.f;
    }
    __syncthreads();
    int tx = tid & 31, ty = tid >> 5;

    unsigned long long acc[4][4];    // [row-pair][col]
    #pragma unroll
    for (int a = 0; a < 4; a++)
        #pragma unroll
        for (int b = 0; b < 4; b++) acc[a][b] = 0ULL;

    #pragma unroll 8
    for (int k = 0; k < 128; k++) {
        float4 wv = ((const float4*)W)[k * 32 + tx];
        unsigned long long wp0, wp1, wp2, wp3;
        PACK2(wp0, wv.x); PACK2(wp1, wv.y); PACK2(wp2, wv.z); PACK2(wp3, wv.w);
        ulonglong2 ha = *(const ulonglong2*)&hsT[k][ty * 8];      // rows (0,1),(2,3)
        ulonglong2 hb = *(const ulonglong2*)&hsT[k][ty * 8 + 4];  // rows (4,5),(6,7)
        FMA2(acc[0][0], ha.x, wp0); FMA2(acc[0][1], ha.x, wp1);
        FMA2(acc[0][2], ha.x, wp2); FMA2(acc[0][3], ha.x, wp3);
        FMA2(acc[1][0], ha.y, wp0); FMA2(acc[1][1], ha.y, wp1);
        FMA2(acc[1][2], ha.y, wp2); FMA2(acc[1][3], ha.y, wp3);
        FMA2(acc[2][0], hb.x, wp0); FMA2(acc[2][1], hb.x, wp1);
        FMA2(acc[2][2], hb.x, wp2); FMA2(acc[2][3], hb.x, wp3);
        FMA2(acc[3][0], hb.y, wp0); FMA2(acc[3][1], hb.y, wp1);
        FMA2(acc[3][2], hb.y, wp2); FMA2(acc[3][3], hb.y, wp3);
    }

    int rbase = row0 + ty * 8;
    #pragma unroll
    for (int rp = 0; rp < 4; rp++) {
        float lo0, hi0, lo1, hi1, lo2, hi2, lo3, hi3;
        UNPACK2(lo0, hi0, acc[rp][0]);
        UNPACK2(lo1, hi1, acc[rp][1]);
        UNPACK2(lo2, hi2, acc[rp][2]);
        UNPACK2(lo3, hi3, acc[rp][3]);
        int r_lo = rbase + 2 * rp;
        if (r_lo < N_NODES) {
            float4 v = {lo0, lo1, lo2, lo3};
            ((float4*)out)[r_lo * 32 + tx] = v;
        }
        if (r_lo + 1 < N_NODES) {
            float4 v = {hi0, hi1, hi2, hi3};
            ((float4*)out)[(r_lo + 1) * 32 + tx] = v;
        }
    }
}

// ============================================================================
// K5: per-dst softmax-weighted gather-sum (single pass; out has self-loop term)
// ============================================================================
__global__ void k_aggregate(const float* __restrict__ h, float* __restrict__ out) {
    int lane = threadIdx.x & 31;
    int n = blockIdx.x * 8 + (threadIdx.x >> 5);
    if (n >= N_NODES) return;
    int beg = g_off[n], end = g_off[n + 1];
    if (beg == end) return;

    float4 acc = {0.f, 0.f, 0.f, 0.f};
    float den = 0.f;
    for (int j = beg; j < end; j++) {
        float ex = g_ex_sorted[j];          // lane-uniform broadcast load
        int src  = g_src_sorted[j];
        den += ex;
        float4 hv = ((const float4*)h)[src * 32 + lane];
        acc.x += ex * hv.x; acc.y += ex * hv.y;
        acc.z += ex * hv.z; acc.w += ex * hv.w;
    }
    float inv = 1.f / den;
    float4* op = (float4*)out + n * 32 + lane;
    float4 o = *op;
    o.x += acc.x * inv; o.y += acc.y * inv;
    o.z += acc.z * inv; o.w += acc.w * inv;
    *op = o;
}

// ---------------- launch ----------------
extern "C" void kernel_launch(void* const* d_in, const int* in_sizes, int n_in,
                              void* d_out, int out_size) {
    const float* h          = (const float*)d_in[0];
    const float* emb_rel    = (const float*)d_in[1];
    const float* attn_fc_w  = (const float*)d_in[2];
    const float* attn_fc2_w = (const float*)d_in[3];
    const float* loop_w     = (const float*)d_in[4];
    const int*   esrc       = (const int*)d_in[5];
    const int*   edst       = (const int*)d_in[6];
    const int*   etype      = (const int*)d_in[7];
    float* out = (float*)d_out;

    k_scores_count<<<SCORE_BLOCKS + COUNT_BLOCKS, 256>>>(h, emb_rel, attn_fc_w, attn_fc2_w, edst);
    k_scan<<<1, 1024>>>();
    k_fill<<<COUNT_BLOCKS, 256>>>(esrc, edst, etype);
    k_gemm<<<(N_NODES + 63) / 64, 256>>>(h, loop_w, out);
    k_aggregate<<<(N_NODES + 7) / 8, 256>>>(h, out);
}

// round 5
// speedup vs baseline: 1.3212x; 1.1221x over previous
#include <cuda_runtime.h>
#include <cuda_bf16.h>
#include <math.h>

#define N_NODES 50000
#define N_EDGES 600000
#define D 128
#define N_RELS 460

#define DEG_PAD 53248               // 1024 threads * 52 (multiple of 4)
#define SCORE_BLOCKS 198            // ceil((N_NODES+N_RELS)/256)
#define COUNT_BLOCKS 586            // ceil(N_EDGES/1024), 4 edges/thread
#define WSPLIT_BLOCKS 64            // 16384 W elements / 256

// ---------------- device scratch ----------------
__device__ int   g_deg[DEG_PAD];
__device__ int   g_off[N_NODES + 1];
__device__ float g_s_src[N_NODES];
__device__ float g_s_dst[N_NODES];
__device__ float g_s_rel[N_RELS];
__device__ float g_ex_sorted[N_EDGES];
__device__ int   g_src_sorted[N_EDGES];
__device__ __nv_bfloat16 g_wThi[D * D];  // loop_weight^T, bf16 hi part, [n][k]
__device__ __nv_bfloat16 g_wTlo[D * D];  // residual lo part

// ---------------- HMMA m16n8k16 bf16, fp32 acc ----------------
#define MMA16816(d, a, b)                                                       \
    asm volatile("mma.sync.aligned.m16n8k16.row.col.f32.bf16.bf16.f32 "         \
        "{%0,%1,%2,%3}, {%4,%5,%6,%7}, {%8,%9}, {%0,%1,%2,%3};"                 \
        : "+f"((d)[0]), "+f"((d)[1]), "+f"((d)[2]), "+f"((d)[3])                \
        : "r"((a)[0]), "r"((a)[1]), "r"((a)[2]), "r"((a)[3]),                   \
          "r"((b)[0]), "r"((b)[1]))

// ============================================================================
// K1: fused scores + degree count + W split.
// ============================================================================
__global__ void k_scores_count(const float* __restrict__ h,
                               const float* __restrict__ emb_rel,
                               const float* __restrict__ W,
                               const float* __restrict__ w2,
                               const int*   __restrict__ edst,
                               const float* __restrict__ loopW) {
    if (blockIdx.x < SCORE_BLOCKS) {
        __shared__ float su[3 * D];
        int t = threadIdx.x;
        {
            float s1 = 0.f, s2 = 0.f;
            #pragma unroll 4
            for (int o = 0; o < D; o++) {
                float c = w2[o];
                s1 += c * W[o * (3 * D) + t];
                if (t < 128) s2 += c * W[o * (3 * D) + t + 256];
            }
            su[t] = s1;
            if (t < 128) su[t + 256] = s2;
        }
        __syncthreads();
        int lane = t & 31;
        int wid  = t >> 5;
        float4 u0 = ((const float4*)su)[lane];
        float4 u1 = ((const float4*)su)[32 + lane];
        float4 u2 = ((const float4*)su)[64 + lane];
        int base = (blockIdx.x * 8 + wid) * 32;
        #pragma unroll 4
        for (int i = 0; i < 32; i++) {
            int gw = base + i;
            if (gw < N_NODES) {
                float4 hv = ((const float4*)h)[gw * 32 + lane];
                float ss = hv.x * u0.x + hv.y * u0.y + hv.z * u0.z + hv.w * u0.w;
                float sd = hv.x * u1.x + hv.y * u1.y + hv.z * u1.z + hv.w * u1.w;
                #pragma unroll
                for (int o = 16; o; o >>= 1) {
                    ss += __shfl_xor_sync(0xffffffffu, ss, o);
                    sd += __shfl_xor_sync(0xffffffffu, sd, o);
                }
                if (lane == 0) { g_s_src[gw] = ss; g_s_dst[gw] = sd; }
            } else if (gw < N_NODES + N_RELS) {
                int r = gw - N_NODES;
                float4 rv = ((const float4*)emb_rel)[r * 32 + lane];
                float sr = rv.x * u2.x + rv.y * u2.y + rv.z * u2.z + rv.w * u2.w;
                #pragma unroll
                for (int o = 16; o; o >>= 1) sr += __shfl_xor_sync(0xffffffffu, sr, o);
                if (lane == 0) g_s_rel[r] = sr;
            }
        }
    } else if (blockIdx.x < SCORE_BLOCKS + COUNT_BLOCKS) {
        int i4 = (blockIdx.x - SCORE_BLOCKS) * 256 + threadIdx.x;
        if (i4 * 4 < N_EDGES) {
            int4 d4 = ((const int4*)edst)[i4];
            atomicAdd(&g_deg[d4.x], 1);
            atomicAdd(&g_deg[d4.y], 1);
            atomicAdd(&g_deg[d4.z], 1);
            atomicAdd(&g_deg[d4.w], 1);
        }
    } else {
        // W split+transpose: g_wT*[n*128+k] = bf16 split of loopW[k*128+n]
        int gid = (blockIdx.x - SCORE_BLOCKS - COUNT_BLOCKS) * 256 + threadIdx.x;
        int n = gid >> 7, k = gid & 127;
        float x = loopW[k * D + n];
        __nv_bfloat16 hi = __float2bfloat16(x);
        __nv_bfloat16 lo = __float2bfloat16(x - __bfloat162float(hi));
        g_wThi[gid] = hi;
        g_wTlo[gid] = lo;
    }
}

// ============================================================================
// K2: single-block exclusive scan
// ============================================================================
__global__ void k_scan() {
    __shared__ int sm[1024];
    int t = threadIdx.x;
    int4 buf[13];
    int s = 0;
    #pragma unroll
    for (int i = 0; i < 13; i++) {
        buf[i] = ((const int4*)g_deg)[t * 13 + i];
        s += buf[i].x + buf[i].y + buf[i].z + buf[i].w;
    }
    sm[t] = s;
    __syncthreads();
    for (int off = 1; off < 1024; off <<= 1) {
        int v = (t >= off) ? sm[t - off] : 0;
        __syncthreads();
        sm[t] += v;
        __syncthreads();
    }
    int pre = sm[t] - s;
    int base = t * 52;
    #pragma unroll
    for (int i = 0; i < 13; i++) {
        int idx = base + i * 4;
        if (idx + 3 <= N_NODES) {
            g_off[idx]     = pre;  pre += buf[i].x;
            g_off[idx + 1] = pre;  pre += buf[i].y;
            g_off[idx + 2] = pre;  pre += buf[i].z;
            g_off[idx + 3] = pre;  pre += buf[i].w;
        } else {
            if (idx     <= N_NODES) g_off[idx]     = pre;  pre += buf[i].x;
            if (idx + 1 <= N_NODES) g_off[idx + 1] = pre;  pre += buf[i].y;
            if (idx + 2 <= N_NODES) g_off[idx + 2] = pre;  pre += buf[i].z;
            if (idx + 3 <= N_NODES) g_off[idx + 3] = pre;  pre += buf[i].w;
        }
    }
}

// ============================================================================
// K3: edge score -> exp, scatter into CSR slots (atomicSub drains g_deg to 0)
// ============================================================================
__global__ void k_fill(const int* __restrict__ esrc, const int* __restrict__ edst,
                       const int* __restrict__ etype) {
    int i4 = blockIdx.x * 256 + threadIdx.x;
    if (i4 * 4 >= N_EDGES) return;
    int4 s4 = ((const int4*)esrc)[i4];
    int4 d4 = ((const int4*)edst)[i4];
    int4 t4 = ((const int4*)etype)[i4];
    #pragma unroll
    for (int j = 0; j < 4; j++) {
        int s = (j == 0) ? s4.x : (j == 1) ? s4.y : (j == 2) ? s4.z : s4.w;
        int d = (j == 0) ? d4.x : (j == 1) ? d4.y : (j == 2) ? d4.z : d4.w;
        int r = (j == 0) ? t4.x : (j == 1) ? t4.y : (j == 2) ? t4.z : t4.w;
        float e = g_s_src[s] + g_s_dst[d] + g_s_rel[r];
        e = (e >= 0.f) ? e : 0.01f * e;
        int pos = g_off[d] + (atomicSub(&g_deg[d], 1) - 1);
        g_ex_sorted[pos]  = __expf(e);
        g_src_sorted[pos] = s;
    }
}

// ============================================================================
// K4: self-loop GEMM via HMMA (mma.sync m16n8k16 bf16), 3-term split precision.
//   CTA: 64 rows x 128 cols, K=128. 8 warps in 2(M) x 4(N) grid, warp tile 32x32.
//   SMEM rows padded to 264B (132 bf16).
// ============================================================================
#define A_STRIDE 264
#define SM_A_HI  0
#define SM_A_LO  (64 * A_STRIDE)            // 16896
#define SM_B_HI  (2 * 64 * A_STRIDE)        // 33792
#define SM_B_LO  (SM_B_HI + 128 * A_STRIDE) // 67584
#define GEMM_SMEM (SM_B_LO + 128 * A_STRIDE) // 101376

__global__ void __launch_bounds__(256, 2) k_gemm_hmma(const float* __restrict__ h,
                                                      float* __restrict__ out) {
    extern __shared__ char sm[];
    int tid = threadIdx.x;
    int row0 = blockIdx.x * 64;

    // ---- A prologue: 64x128 f32 -> bf16 hi/lo (32 x 8B chunks per row) ----
    #pragma unroll
    for (int i = 0; i < 8; i++) {
        int idx = tid + i * 256;
        int r = idx >> 5, c4 = idx & 31;
        int row = row0 + r;
        float4 v = (row < N_NODES) ? ((const float4*)h)[row * 32 + c4]
                                   : make_float4(0.f, 0.f, 0.f, 0.f);
        __nv_bfloat162 h01 = __floats2bfloat162_rn(v.x, v.y);
        __nv_bfloat162 h23 = __floats2bfloat162_rn(v.z, v.w);
        float lx = v.x - __bfloat162float(__low2bfloat16(h01));
        float ly = v.y - __bfloat162float(__high2bfloat16(h01));
        float lz = v.z - __bfloat162float(__low2bfloat16(h23));
        float lw = v.w - __bfloat162float(__high2bfloat16(h23));
        __nv_bfloat162 l01 = __floats2bfloat162_rn(lx, ly);
        __nv_bfloat162 l23 = __floats2bfloat162_rn(lz, lw);
        unsigned off = r * A_STRIDE + c4 * 8;
        *(uint2*)(sm + SM_A_HI + off) = make_uint2(*(unsigned*)&h01, *(unsigned*)&h23);
        *(uint2*)(sm + SM_A_LO + off) = make_uint2(*(unsigned*)&l01, *(unsigned*)&l23);
    }

    // ---- B prologue: copy pre-split W^T bf16 [n][k] into padded smem ----
    // 128 rows x 32 uint2 chunks per row (128 bf16 = 256 B) = 4096 chunks
    #pragma unroll
    for (int i = 0; i < 16; i++) {
        int idx = tid + i * 256;              // idx = n*32 + kc
        int n = idx >> 5, kc = idx & 31;
        unsigned off = n * A_STRIDE + kc * 8;
        *(uint2*)(sm + SM_B_HI + off) = ((const uint2*)g_wThi)[idx];
        *(uint2*)(sm + SM_B_LO + off) = ((const uint2*)g_wTlo)[idx];
    }
    __syncthreads();

    int lane = tid & 31, wid = tid >> 5;
    int g = lane >> 2, t = lane & 3;
    int wm = (wid & 1) * 32;       // warp M offset (2 warps along M)
    int wn = (wid >> 1) * 32;      // warp N offset (4 warps along N)

    float acc[2][4][4];
    #pragma unroll
    for (int a = 0; a < 2; a++)
        #pragma unroll
        for (int b = 0; b < 4; b++)
            #pragma unroll
            for (int c = 0; c < 4; c++) acc[a][b][c] = 0.f;

    #pragma unroll
    for (int ks = 0; ks < 8; ks++) {
        int kbyte = ks * 32 + t * 4;           // (k0 + 2t) * 2 bytes
        unsigned ahi[2][4], alo[2][4];
        #pragma unroll
        for (int mt = 0; mt < 2; mt++) {
            int rb = (wm + mt * 16 + g) * A_STRIDE + kbyte;
            ahi[mt][0] = *(const unsigned*)(sm + SM_A_HI + rb);
            ahi[mt][1] = *(const unsigned*)(sm + SM_A_HI + rb + 8 * A_STRIDE);
            ahi[mt][2] = *(const unsigned*)(sm + SM_A_HI + rb + 16);
            ahi[mt][3] = *(const unsigned*)(sm + SM_A_HI + rb + 8 * A_STRIDE + 16);
            alo[mt][0] = *(const unsigned*)(sm + SM_A_LO + rb);
            alo[mt][1] = *(const unsigned*)(sm + SM_A_LO + rb + 8 * A_STRIDE);
            alo[mt][2] = *(const unsigned*)(sm + SM_A_LO + rb + 16);
            alo[mt][3] = *(const unsigned*)(sm + SM_A_LO + rb + 8 * A_STRIDE + 16);
        }
        #pragma unroll
        for (int nt = 0; nt < 4; nt++) {
            int nb = (wn + nt * 8 + g) * A_STRIDE + kbyte;
            unsigned bhi[2], blo[2];
            bhi[0] = *(const unsigned*)(sm + SM_B_HI + nb);
            bhi[1] = *(const unsigned*)(sm + SM_B_HI + nb + 16);
            blo[0] = *(const unsigned*)(sm + SM_B_LO + nb);
            blo[1] = *(const unsigned*)(sm + SM_B_LO + nb + 16);
            #pragma unroll
            for (int mt = 0; mt < 2; mt++) {
                MMA16816(acc[mt][nt], ahi[mt], bhi);
                MMA16816(acc[mt][nt], ahi[mt], blo);
                MMA16816(acc[mt][nt], alo[mt], bhi);
            }
        }
    }

    // ---- epilogue: direct global stores ----
    #pragma unroll
    for (int mt = 0; mt < 2; mt++) {
        int r0 = row0 + wm + mt * 16 + g;
        #pragma unroll
        for (int nt = 0; nt < 4; nt++) {
            int col = wn + nt * 8 + 2 * t;
            if (r0 < N_NODES)
                *(float2*)(out + r0 * D + col) = make_float2(acc[mt][nt][0], acc[mt][nt][1]);
            if (r0 + 8 < N_NODES)
                *(float2*)(out + (r0 + 8) * D + col) = make_float2(acc[mt][nt][2], acc[mt][nt][3]);
        }
    }
}

// ============================================================================
// K5: per-dst softmax-weighted gather-sum
// ============================================================================
__global__ void k_aggregate(const float* __restrict__ h, float* __restrict__ out) {
    int lane = threadIdx.x & 31;
    int n = blockIdx.x * 8 + (threadIdx.x >> 5);
    if (n >= N_NODES) return;
    int beg = g_off[n], end = g_off[n + 1];
    if (beg == end) return;

    float4 acc = {0.f, 0.f, 0.f, 0.f};
    float den = 0.f;
    for (int j = beg; j < end; j++) {
        float ex = g_ex_sorted[j];
        int src  = g_src_sorted[j];
        den += ex;
        float4 hv = ((const float4*)h)[src * 32 + lane];
        acc.x += ex * hv.x; acc.y += ex * hv.y;
        acc.z += ex * hv.z; acc.w += ex * hv.w;
    }
    float inv = 1.f / den;
    float4* op = (float4*)out + n * 32 + lane;
    float4 o = *op;
    o.x += acc.x * inv; o.y += acc.y * inv;
    o.z += acc.z * inv; o.w += acc.w * inv;
    *op = o;
}

// ---------------- launch ----------------
extern "C" void kernel_launch(void* const* d_in, const int* in_sizes, int n_in,
                              void* d_out, int out_size) {
    const float* h          = (const float*)d_in[0];
    const float* emb_rel    = (const float*)d_in[1];
    const float* attn_fc_w  = (const float*)d_in[2];
    const float* attn_fc2_w = (const float*)d_in[3];
    const float* loop_w     = (const float*)d_in[4];
    const int*   esrc       = (const int*)d_in[5];
    const int*   edst       = (const int*)d_in[6];
    const int*   etype      = (const int*)d_in[7];
    float* out = (float*)d_out;

    cudaFuncSetAttribute(k_gemm_hmma, cudaFuncAttributeMaxDynamicSharedMemorySize, GEMM_SMEM);

    k_scores_count<<<SCORE_BLOCKS + COUNT_BLOCKS + WSPLIT_BLOCKS, 256>>>(
        h, emb_rel, attn_fc_w, attn_fc2_w, edst, loop_w);
    k_scan<<<1, 1024>>>();
    k_fill<<<COUNT_BLOCKS, 256>>>(esrc, edst, etype);
    k_gemm_hmma<<<(N_NODES + 63) / 64, 256, GEMM_SMEM>>>(h, out);
    k_aggregate<<<(N_NODES + 7) / 8, 256>>>(h, out);
}

// round 6
// speedup vs baseline: 1.4615x; 1.1062x over previous
#include <cuda_runtime.h>
#include <cuda_bf16.h>
#include <math.h>

#define N_NODES 50000
#define N_EDGES 600000
#define D 128
#define N_RELS 460

#define DEG_PAD 53248               // 13 blocks * 1024 threads * 4 items
#define SCAN_BLOCKS 13
#define SCORE_BLOCKS 198            // ceil((N_NODES+N_RELS)/256)
#define COUNT_BLOCKS 586            // ceil(N_EDGES/1024), 4 edges/thread
#define WSPLIT_BLOCKS 64            // 16384 W elements / 256

// ---------------- device scratch ----------------
__device__ __align__(16) int g_deg[DEG_PAD];
__device__ __align__(16) int g_off[DEG_PAD];     // exclusive prefix (padded; [N_NODES] valid)
__device__ int   g_scan_pub[SCAN_BLOCKS];        // inclusive+1; 0 = not ready (reset each replay)
__device__ float g_s_src[N_NODES];
__device__ float g_s_dst[N_NODES];
__device__ float g_s_rel[N_RELS];
__device__ __align__(8) uint2 g_edge[N_EDGES];   // {exp(score) bits, src}, grouped by dst
__device__ __nv_bfloat16 g_wThi[D * D];          // loop_weight^T bf16 hi, [n][k]
__device__ __nv_bfloat16 g_wTlo[D * D];          // residual lo

// ---------------- HMMA m16n8k16 bf16, fp32 acc ----------------
#define MMA16816(d, a, b)                                                       \
    asm volatile("mma.sync.aligned.m16n8k16.row.col.f32.bf16.bf16.f32 "         \
        "{%0,%1,%2,%3}, {%4,%5,%6,%7}, {%8,%9}, {%0,%1,%2,%3};"                 \
        : "+f"((d)[0]), "+f"((d)[1]), "+f"((d)[2]), "+f"((d)[3])                \
        : "r"((a)[0]), "r"((a)[1]), "r"((a)[2]), "r"((a)[3]),                   \
          "r"((b)[0]), "r"((b)[1]))

#define LDSM4(r, a)                                                             \
    asm volatile("ldmatrix.sync.aligned.m8n8.x4.shared.b16 {%0,%1,%2,%3}, [%4];" \
        : "=r"((r)[0]), "=r"((r)[1]), "=r"((r)[2]), "=r"((r)[3]) : "r"(a))

__device__ __forceinline__ unsigned smem_u32(const void* p) {
    unsigned a;
    asm("{ .reg .u64 t; cvta.to.shared.u64 t, %1; cvt.u32.u64 %0, t; }" : "=r"(a) : "l"(p));
    return a;
}

// ============================================================================
// K1: fused scores + degree count + W split + scan-flag reset.
// ============================================================================
__global__ void k_scores_count(const float* __restrict__ h,
                               const float* __restrict__ emb_rel,
                               const float* __restrict__ W,
                               const float* __restrict__ w2,
                               const int*   __restrict__ edst,
                               const float* __restrict__ loopW) {
    if (blockIdx.x < SCORE_BLOCKS) {
        __shared__ float su[3 * D];
        int t = threadIdx.x;
        {
            float s1 = 0.f, s2 = 0.f;
            #pragma unroll 4
            for (int o = 0; o < D; o++) {
                float c = w2[o];
                s1 += c * W[o * (3 * D) + t];
                if (t < 128) s2 += c * W[o * (3 * D) + t + 256];
            }
            su[t] = s1;
            if (t < 128) su[t + 256] = s2;
        }
        __syncthreads();
        int lane = t & 31;
        int wid  = t >> 5;
        float4 u0 = ((const float4*)su)[lane];
        float4 u1 = ((const float4*)su)[32 + lane];
        float4 u2 = ((const float4*)su)[64 + lane];
        int base = (blockIdx.x * 8 + wid) * 32;
        #pragma unroll 4
        for (int i = 0; i < 32; i++) {
            int gw = base + i;
            if (gw < N_NODES) {
                float4 hv = ((const float4*)h)[gw * 32 + lane];
                float ss = hv.x * u0.x + hv.y * u0.y + hv.z * u0.z + hv.w * u0.w;
                float sd = hv.x * u1.x + hv.y * u1.y + hv.z * u1.z + hv.w * u1.w;
                #pragma unroll
                for (int o = 16; o; o >>= 1) {
                    ss += __shfl_xor_sync(0xffffffffu, ss, o);
                    sd += __shfl_xor_sync(0xffffffffu, sd, o);
                }
                if (lane == 0) { g_s_src[gw] = ss; g_s_dst[gw] = sd; }
            } else if (gw < N_NODES + N_RELS) {
                int r = gw - N_NODES;
                float4 rv = ((const float4*)emb_rel)[r * 32 + lane];
                float sr = rv.x * u2.x + rv.y * u2.y + rv.z * u2.z + rv.w * u2.w;
                #pragma unroll
                for (int o = 16; o; o >>= 1) sr += __shfl_xor_sync(0xffffffffu, sr, o);
                if (lane == 0) g_s_rel[r] = sr;
            }
        }
    } else if (blockIdx.x < SCORE_BLOCKS + COUNT_BLOCKS) {
        int i4 = (blockIdx.x - SCORE_BLOCKS) * 256 + threadIdx.x;
        if (i4 * 4 < N_EDGES) {
            int4 d4 = ((const int4*)edst)[i4];
            atomicAdd(&g_deg[d4.x], 1);
            atomicAdd(&g_deg[d4.y], 1);
            atomicAdd(&g_deg[d4.z], 1);
            atomicAdd(&g_deg[d4.w], 1);
        }
    } else {
        // W split+transpose + scan-flag reset (runs before k_scan in stream order)
        int gid = (blockIdx.x - SCORE_BLOCKS - COUNT_BLOCKS) * 256 + threadIdx.x;
        if (gid < SCAN_BLOCKS) g_scan_pub[gid] = 0;
        int n = gid >> 7, k = gid & 127;
        float x = loopW[k * D + n];
        __nv_bfloat16 hi = __float2bfloat16(x);
        __nv_bfloat16 lo = __float2bfloat16(x - __bfloat162float(hi));
        g_wThi[gid] = hi;
        g_wTlo[gid] = lo;
    }
}

// ============================================================================
// K2: decoupled-lookback exclusive scan, 13 blocks x 1024 thr x 4 items.
//   Coalesced int4 loads/stores; single-word publish (inclusive+1).
// ============================================================================
__global__ void __launch_bounds__(1024) k_scan() {
    __shared__ int sm[1024];
    __shared__ int s_prefix;
    int b = blockIdx.x, t = threadIdx.x;
    int4 v = ((const int4*)g_deg)[b * 1024 + t];
    int tot = v.x + v.y + v.z + v.w;
    sm[t] = tot;
    __syncthreads();
    #pragma unroll
    for (int off = 1; off < 1024; off <<= 1) {
        int val = (t >= off) ? sm[t - off] : 0;
        __syncthreads();
        sm[t] += val;
        __syncthreads();
    }
    if (t == 1023) {
        int inc = sm[1023];          // block total
        int p = 0;
        if (b > 0) {
            volatile int* pub = g_scan_pub;
            int x;
            do { x = pub[b - 1]; } while (x == 0);
            p = x - 1;
        }
        ((volatile int*)g_scan_pub)[b] = p + inc + 1;
        s_prefix = p;
    }
    __syncthreads();
    int pre = s_prefix + sm[t] - tot;   // exclusive prefix of this thread's 4 items
    int4 o;
    o.x = pre;
    o.y = pre + v.x;
    o.z = o.y + v.y;
    o.w = o.z + v.z;
    ((int4*)g_off)[b * 1024 + t] = o;
}

// ============================================================================
// K3: edge score -> exp, scatter packed {ex, src} into CSR slots.
//   atomicSub drains g_deg back to 0 for the next graph replay.
// ============================================================================
__global__ void k_fill(const int* __restrict__ esrc, const int* __restrict__ edst,
                       const int* __restrict__ etype) {
    int i4 = blockIdx.x * 256 + threadIdx.x;
    if (i4 * 4 >= N_EDGES) return;
    int4 s4 = ((const int4*)esrc)[i4];
    int4 d4 = ((const int4*)edst)[i4];
    int4 t4 = ((const int4*)etype)[i4];
    #pragma unroll
    for (int j = 0; j < 4; j++) {
        int s = (j == 0) ? s4.x : (j == 1) ? s4.y : (j == 2) ? s4.z : s4.w;
        int d = (j == 0) ? d4.x : (j == 1) ? d4.y : (j == 2) ? d4.z : d4.w;
        int r = (j == 0) ? t4.x : (j == 1) ? t4.y : (j == 2) ? t4.z : t4.w;
        float e = g_s_src[s] + g_s_dst[d] + g_s_rel[r];
        e = (e >= 0.f) ? e : 0.01f * e;
        int pos = g_off[d] + (atomicSub(&g_deg[d], 1) - 1);
        g_edge[pos] = make_uint2(__float_as_uint(__expf(e)), (unsigned)s);
    }
}

// ============================================================================
// K4: self-loop GEMM via HMMA, 3-term bf16 split precision.
//   A (h tile, hi/lo) in smem via ldmatrix.x4; B (W^T bf16) direct LDG (L1-res).
//   CTA 64x128, 8 warps (2M x 4N), warp tile 32x32, smem 34.8KB.
// ============================================================================
#define A_STRIDE 272                        // 17*16: 16B-aligned rows, ldmatrix conflict-free
#define SM_A_HI  0
#define SM_A_LO  (64 * A_STRIDE)            // 17408
#define GEMM_SMEM (2 * 64 * A_STRIDE)       // 34816

__global__ void __launch_bounds__(256) k_gemm_hmma(const float* __restrict__ h,
                                                   float* __restrict__ out) {
    extern __shared__ char smc[];
    unsigned sb = smem_u32(smc);
    int tid = threadIdx.x;
    int row0 = blockIdx.x * 64;

    // ---- A prologue: 64x128 f32 -> bf16 hi/lo ----
    #pragma unroll
    for (int i = 0; i < 8; i++) {
        int idx = tid + i * 256;
        int r = idx >> 5, c4 = idx & 31;
        int row = row0 + r;
        float4 v = (row < N_NODES) ? ((const float4*)h)[row * 32 + c4]
                                   : make_float4(0.f, 0.f, 0.f, 0.f);
        __nv_bfloat162 h01 = __floats2bfloat162_rn(v.x, v.y);
        __nv_bfloat162 h23 = __floats2bfloat162_rn(v.z, v.w);
        float lx = v.x - __bfloat162float(__low2bfloat16(h01));
        float ly = v.y - __bfloat162float(__high2bfloat16(h01));
        float lz = v.z - __bfloat162float(__low2bfloat16(h23));
        float lw = v.w - __bfloat162float(__high2bfloat16(h23));
        __nv_bfloat162 l01 = __floats2bfloat162_rn(lx, ly);
        __nv_bfloat162 l23 = __floats2bfloat162_rn(lz, lw);
        unsigned off = r * A_STRIDE + c4 * 8;
        *(uint2*)(smc + SM_A_HI + off) = make_uint2(*(unsigned*)&h01, *(unsigned*)&h23);
        *(uint2*)(smc + SM_A_LO + off) = make_uint2(*(unsigned*)&l01, *(unsigned*)&l23);
    }
    __syncthreads();

    int lane = tid & 31, wid = tid >> 5;
    int g = lane >> 2, t = lane & 3;
    int wm = (wid & 1) * 32;
    int wn = (wid >> 1) * 32;

    // ldmatrix per-lane address: rows (lane&15), k-half select (lane>>4)
    unsigned aAddr = sb + SM_A_HI + (wm + (lane & 15)) * A_STRIDE + (lane >> 4) * 16;

    const __nv_bfloat16* __restrict__ wh = g_wThi;
    const __nv_bfloat16* __restrict__ wl = g_wTlo;
    int bbase[4];
    #pragma unroll
    for (int nt = 0; nt < 4; nt++) bbase[nt] = (wn + nt * 8 + g) * D + 2 * t;

    float acc[2][4][4];
    #pragma unroll
    for (int a = 0; a < 2; a++)
        #pragma unroll
        for (int b2 = 0; b2 < 4; b2++)
            #pragma unroll
            for (int c = 0; c < 4; c++) acc[a][b2][c] = 0.f;

    #pragma unroll
    for (int ks = 0; ks < 8; ks++) {
        unsigned ahi[2][4], alo[2][4];
        #pragma unroll
        for (int mt = 0; mt < 2; mt++) {
            unsigned addr = aAddr + mt * (16 * A_STRIDE) + ks * 32;
            LDSM4(ahi[mt], addr);
            LDSM4(alo[mt], addr + (unsigned)SM_A_LO);
        }
        #pragma unroll
        for (int nt = 0; nt < 4; nt++) {
            int k0 = bbase[nt] + ks * 16;
            unsigned bhi[2], blo[2];
            bhi[0] = *(const unsigned*)(wh + k0);
            bhi[1] = *(const unsigned*)(wh + k0 + 8);
            blo[0] = *(const unsigned*)(wl + k0);
            blo[1] = *(const unsigned*)(wl + k0 + 8);
            #pragma unroll
            for (int mt = 0; mt < 2; mt++) {
                MMA16816(acc[mt][nt], ahi[mt], bhi);
                MMA16816(acc[mt][nt], ahi[mt], blo);
                MMA16816(acc[mt][nt], alo[mt], bhi);
            }
        }
    }

    // ---- epilogue ----
    #pragma unroll
    for (int mt = 0; mt < 2; mt++) {
        int r0 = row0 + wm + mt * 16 + g;
        #pragma unroll
        for (int nt = 0; nt < 4; nt++) {
            int col = wn + nt * 8 + 2 * t;
            if (r0 < N_NODES)
                *(float2*)(out + r0 * D + col) = make_float2(acc[mt][nt][0], acc[mt][nt][1]);
            if (r0 + 8 < N_NODES)
                *(float2*)(out + (r0 + 8) * D + col) = make_float2(acc[mt][nt][2], acc[mt][nt][3]);
        }
    }
}

// ============================================================================
// K5: per-dst softmax-weighted gather-sum (2x unrolled for MLP)
// ============================================================================
__global__ void k_aggregate(const float* __restrict__ h, float* __restrict__ out) {
    int lane = threadIdx.x & 31;
    int n = blockIdx.x * 8 + (threadIdx.x >> 5);
    if (n >= N_NODES) return;
    int beg = g_off[n], end = g_off[n + 1];
    if (beg == end) return;

    float4 acc = {0.f, 0.f, 0.f, 0.f};
    float den = 0.f;
    int j = beg;
    for (; j + 2 <= end; j += 2) {
        uint2 e0 = g_edge[j], e1 = g_edge[j + 1];
        float4 h0 = ((const float4*)h)[e0.y * 32 + lane];
        float4 h1 = ((const float4*)h)[e1.y * 32 + lane];
        float x0 = __uint_as_float(e0.x), x1 = __uint_as_float(e1.x);
        den += x0 + x1;
        acc.x += x0 * h0.x + x1 * h1.x;
        acc.y += x0 * h0.y + x1 * h1.y;
        acc.z += x0 * h0.z + x1 * h1.z;
        acc.w += x0 * h0.w + x1 * h1.w;
    }
    if (j < end) {
        uint2 e0 = g_edge[j];
        float4 h0 = ((const float4*)h)[e0.y * 32 + lane];
        float x0 = __uint_as_float(e0.x);
        den += x0;
        acc.x += x0 * h0.x; acc.y += x0 * h0.y;
        acc.z += x0 * h0.z; acc.w += x0 * h0.w;
    }
    float inv = 1.f / den;
    float4* op = (float4*)out + n * 32 + lane;
    float4 o = *op;
    o.x += acc.x * inv; o.y += acc.y * inv;
    o.z += acc.z * inv; o.w += acc.w * inv;
    *op = o;
}

// ---------------- launch ----------------
extern "C" void kernel_launch(void* const* d_in, const int* in_sizes, int n_in,
                              void* d_out, int out_size) {
    const float* h          = (const float*)d_in[0];
    const float* emb_rel    = (const float*)d_in[1];
    const float* attn_fc_w  = (const float*)d_in[2];
    const float* attn_fc2_w = (const float*)d_in[3];
    const float* loop_w     = (const float*)d_in[4];
    const int*   esrc       = (const int*)d_in[5];
    const int*   edst       = (const int*)d_in[6];
    const int*   etype      = (const int*)d_in[7];
    float* out = (float*)d_out;

    cudaFuncSetAttribute(k_gemm_hmma, cudaFuncAttributeMaxDynamicSharedMemorySize, GEMM_SMEM);

    k_scores_count<<<SCORE_BLOCKS + COUNT_BLOCKS + WSPLIT_BLOCKS, 256>>>(
        h, emb_rel, attn_fc_w, attn_fc2_w, edst, loop_w);
    k_scan<<<SCAN_BLOCKS, 1024>>>();
    k_fill<<<COUNT_BLOCKS, 256>>>(esrc, edst, etype);
    k_gemm_hmma<<<(N_NODES + 63) / 64, 256, GEMM_SMEM>>>(h, out);
    k_aggregate<<<(N_NODES + 7) / 8, 256>>>(h, out);
}

// round 7
// speedup vs baseline: 1.7876x; 1.2231x over previous
#include <cuda_runtime.h>
#include <cuda_bf16.h>
#include <math.h>

#define N_NODES 50000
#define N_EDGES 600000
#define D 128
#define N_RELS 460

#define DEG_PAD 53248               // 13 blocks * 1024 threads * 4 items
#define SCAN_BLOCKS 13
#define SCORE_BLOCKS 198            // ceil((N_NODES+N_RELS)/256)
#define COUNT_BLOCKS 586            // ceil(N_EDGES/1024), 4 edges/thread
#define WSPLIT_BLOCKS 16            // 4096 fragment uint4s / 256

// ---------------- device scratch ----------------
__device__ __align__(16) int g_deg[DEG_PAD];
__device__ __align__(16) int g_off[DEG_PAD];     // exclusive prefix (padded; [N_NODES] valid)
__device__ int   g_scan_pub[SCAN_BLOCKS];        // inclusive+1; 0 = not ready (reset each replay)
__device__ float g_s_src[N_NODES];
__device__ float g_s_dst[N_NODES];
__device__ float g_s_rel[N_RELS];
__device__ __align__(8) uint2 g_edge[N_EDGES];   // {exp(score) bits, src}, grouped by dst
// W^T in HMMA b-fragment order: [ntile(16)][ks(8)][lane(32)] = {bhi0,bhi1,blo0,blo1}
__device__ __align__(16) uint4 g_wfrag[16 * 8 * 32];

// ---------------- HMMA m16n8k16 bf16, fp32 acc ----------------
#define MMA16816(d, a, b0, b1)                                                  \
    asm volatile("mma.sync.aligned.m16n8k16.row.col.f32.bf16.bf16.f32 "         \
        "{%0,%1,%2,%3}, {%4,%5,%6,%7}, {%8,%9}, {%0,%1,%2,%3};"                 \
        : "+f"((d)[0]), "+f"((d)[1]), "+f"((d)[2]), "+f"((d)[3])                \
        : "r"((a)[0]), "r"((a)[1]), "r"((a)[2]), "r"((a)[3]),                   \
          "r"(b0), "r"(b1))

#define LDSM4(r, a)                                                             \
    asm volatile("ldmatrix.sync.aligned.m8n8.x4.shared.b16 {%0,%1,%2,%3}, [%4];" \
        : "=r"((r)[0]), "=r"((r)[1]), "=r"((r)[2]), "=r"((r)[3]) : "r"(a))

__device__ __forceinline__ unsigned smem_u32(const void* p) {
    unsigned a;
    asm("{ .reg .u64 t; cvta.to.shared.u64 t, %1; cvt.u32.u64 %0, t; }" : "=r"(a) : "l"(p));
    return a;
}
__device__ __forceinline__ unsigned pack_hi(float a, float b) {
    __nv_bfloat162 v = __floats2bfloat162_rn(a, b);
    return *(unsigned*)&v;
}

// ============================================================================
// K1: fused scores + degree count + W fragment-split + scan-flag reset.
// ============================================================================
__global__ void k_scores_count(const float* __restrict__ h,
                               const float* __restrict__ emb_rel,
                               const float* __restrict__ W,
                               const float* __restrict__ w2,
                               const int*   __restrict__ edst,
                               const float* __restrict__ loopW) {
    if (blockIdx.x < SCORE_BLOCKS) {
        __shared__ float su[3 * D];
        int t = threadIdx.x;
        {
            float s1 = 0.f, s2 = 0.f;
            #pragma unroll 4
            for (int o = 0; o < D; o++) {
                float c = w2[o];
                s1 += c * W[o * (3 * D) + t];
                if (t < 128) s2 += c * W[o * (3 * D) + t + 256];
            }
            su[t] = s1;
            if (t < 128) su[t + 256] = s2;
        }
        __syncthreads();
        int lane = t & 31;
        int wid  = t >> 5;
        float4 u0 = ((const float4*)su)[lane];
        float4 u1 = ((const float4*)su)[32 + lane];
        float4 u2 = ((const float4*)su)[64 + lane];
        int base = (blockIdx.x * 8 + wid) * 32;
        #pragma unroll 4
        for (int i = 0; i < 32; i++) {
            int gw = base + i;
            if (gw < N_NODES) {
                float4 hv = ((const float4*)h)[gw * 32 + lane];
                float ss = hv.x * u0.x + hv.y * u0.y + hv.z * u0.z + hv.w * u0.w;
                float sd = hv.x * u1.x + hv.y * u1.y + hv.z * u1.z + hv.w * u1.w;
                #pragma unroll
                for (int o = 16; o; o >>= 1) {
                    ss += __shfl_xor_sync(0xffffffffu, ss, o);
                    sd += __shfl_xor_sync(0xffffffffu, sd, o);
                }
                if (lane == 0) { g_s_src[gw] = ss; g_s_dst[gw] = sd; }
            } else if (gw < N_NODES + N_RELS) {
                int r = gw - N_NODES;
                float4 rv = ((const float4*)emb_rel)[r * 32 + lane];
                float sr = rv.x * u2.x + rv.y * u2.y + rv.z * u2.z + rv.w * u2.w;
                #pragma unroll
                for (int o = 16; o; o >>= 1) sr += __shfl_xor_sync(0xffffffffu, sr, o);
                if (lane == 0) g_s_rel[r] = sr;
            }
        }
    } else if (blockIdx.x < SCORE_BLOCKS + COUNT_BLOCKS) {
        int i4 = (blockIdx.x - SCORE_BLOCKS) * 256 + threadIdx.x;
        if (i4 * 4 < N_EDGES) {
            int4 d4 = ((const int4*)edst)[i4];
            atomicAdd(&g_deg[d4.x], 1);
            atomicAdd(&g_deg[d4.y], 1);
            atomicAdd(&g_deg[d4.z], 1);
            atomicAdd(&g_deg[d4.w], 1);
        }
    } else {
        // W -> HMMA b-fragment table (+ scan-flag reset); runs before k_scan
        int gid = (blockIdx.x - SCORE_BLOCKS - COUNT_BLOCKS) * 256 + threadIdx.x;
        if (gid < SCAN_BLOCKS) g_scan_pub[gid] = 0;
        int ntile = gid >> 8;            // 0..15
        int ks    = (gid >> 5) & 7;      // 0..7
        int lane  = gid & 31;
        int g = lane >> 2, t = lane & 3;
        int n  = ntile * 8 + g;
        int k0 = ks * 16 + 2 * t;
        float w00 = loopW[k0 * D + n];
        float w01 = loopW[(k0 + 1) * D + n];
        float w80 = loopW[(k0 + 8) * D + n];
        float w81 = loopW[(k0 + 9) * D + n];
        unsigned hi0 = pack_hi(w00, w01);
        unsigned hi1 = pack_hi(w80, w81);
        __nv_bfloat162 h0 = *(__nv_bfloat162*)&hi0;
        __nv_bfloat162 h1 = *(__nv_bfloat162*)&hi1;
        unsigned lo0 = pack_hi(w00 - __bfloat162float(__low2bfloat16(h0)),
                               w01 - __bfloat162float(__high2bfloat16(h0)));
        unsigned lo1 = pack_hi(w80 - __bfloat162float(__low2bfloat16(h1)),
                               w81 - __bfloat162float(__high2bfloat16(h1)));
        g_wfrag[gid] = make_uint4(hi0, hi1, lo0, lo1);
    }
}

// ============================================================================
// K2: decoupled-lookback exclusive scan, 13 blocks x 1024 thr x 4 items.
// ============================================================================
__global__ void __launch_bounds__(1024) k_scan() {
    __shared__ int sm[1024];
    __shared__ int s_prefix;
    int b = blockIdx.x, t = threadIdx.x;
    int4 v = ((const int4*)g_deg)[b * 1024 + t];
    int tot = v.x + v.y + v.z + v.w;
    sm[t] = tot;
    __syncthreads();
    #pragma unroll
    for (int off = 1; off < 1024; off <<= 1) {
        int val = (t >= off) ? sm[t - off] : 0;
        __syncthreads();
        sm[t] += val;
        __syncthreads();
    }
    if (t == 1023) {
        int inc = sm[1023];
        int p = 0;
        if (b > 0) {
            volatile int* pub = g_scan_pub;
            int x;
            do { x = pub[b - 1]; } while (x == 0);
            p = x - 1;
        }
        ((volatile int*)g_scan_pub)[b] = p + inc + 1;
        s_prefix = p;
    }
    __syncthreads();
    int pre = s_prefix + sm[t] - tot;
    int4 o;
    o.x = pre;
    o.y = pre + v.x;
    o.z = o.y + v.y;
    o.w = o.z + v.z;
    ((int4*)g_off)[b * 1024 + t] = o;
}

// ============================================================================
// K3: edge score -> exp, scatter packed {ex, src} into CSR slots.
// ============================================================================
__global__ void k_fill(const int* __restrict__ esrc, const int* __restrict__ edst,
                       const int* __restrict__ etype) {
    int i4 = blockIdx.x * 256 + threadIdx.x;
    if (i4 * 4 >= N_EDGES) return;
    int4 s4 = ((const int4*)esrc)[i4];
    int4 d4 = ((const int4*)edst)[i4];
    int4 t4 = ((const int4*)etype)[i4];
    #pragma unroll
    for (int j = 0; j < 4; j++) {
        int s = (j == 0) ? s4.x : (j == 1) ? s4.y : (j == 2) ? s4.z : s4.w;
        int d = (j == 0) ? d4.x : (j == 1) ? d4.y : (j == 2) ? d4.z : d4.w;
        int r = (j == 0) ? t4.x : (j == 1) ? t4.y : (j == 2) ? t4.z : t4.w;
        float e = g_s_src[s] + g_s_dst[d] + g_s_rel[r];
        e = (e >= 0.f) ? e : 0.01f * e;
        int pos = g_off[d] + (atomicSub(&g_deg[d], 1) - 1);
        g_edge[pos] = make_uint2(__float_as_uint(__expf(e)), (unsigned)s);
    }
}

// ============================================================================
// K4: self-loop GEMM via HMMA, 3-term bf16 split precision.
//   A (h tile hi/lo) in smem via ldmatrix.x4; B via fragment table (LDG.128).
//   CTA 64x128, 8 warps (2M x 4N), warp tile 32x32, smem 34.8KB.
// ============================================================================
#define A_STRIDE 272                        // 17*16: 16B-aligned rows
#define SM_A_HI  0
#define SM_A_LO  (64 * A_STRIDE)            // 17408
#define GEMM_SMEM (2 * 64 * A_STRIDE)       // 34816

__global__ void __launch_bounds__(256) k_gemm_hmma(const float* __restrict__ h,
                                                   float* __restrict__ out) {
    extern __shared__ char smc[];
    unsigned sb = smem_u32(smc);
    int tid = threadIdx.x;
    int row0 = blockIdx.x * 64;

    // ---- A prologue: 64x128 f32 -> bf16 hi/lo ----
    #pragma unroll
    for (int i = 0; i < 8; i++) {
        int idx = tid + i * 256;
        int r = idx >> 5, c4 = idx & 31;
        int row = row0 + r;
        float4 v = (row < N_NODES) ? ((const float4*)h)[row * 32 + c4]
                                   : make_float4(0.f, 0.f, 0.f, 0.f);
        __nv_bfloat162 h01 = __floats2bfloat162_rn(v.x, v.y);
        __nv_bfloat162 h23 = __floats2bfloat162_rn(v.z, v.w);
        float lx = v.x - __bfloat162float(__low2bfloat16(h01));
        float ly = v.y - __bfloat162float(__high2bfloat16(h01));
        float lz = v.z - __bfloat162float(__low2bfloat16(h23));
        float lw = v.w - __bfloat162float(__high2bfloat16(h23));
        __nv_bfloat162 l01 = __floats2bfloat162_rn(lx, ly);
        __nv_bfloat162 l23 = __floats2bfloat162_rn(lz, lw);
        unsigned off = r * A_STRIDE + c4 * 8;
        *(uint2*)(smc + SM_A_HI + off) = make_uint2(*(unsigned*)&h01, *(unsigned*)&h23);
        *(uint2*)(smc + SM_A_LO + off) = make_uint2(*(unsigned*)&l01, *(unsigned*)&l23);
    }
    __syncthreads();

    int lane = tid & 31, wid = tid >> 5;
    int g = lane >> 2, t = lane & 3;
    int wm = (wid & 1) * 32;
    int wn = (wid >> 1) * 32;

    unsigned aAddr = sb + SM_A_HI + (wm + (lane & 15)) * A_STRIDE + (lane >> 4) * 16;
    const uint4* __restrict__ wf = g_wfrag + (wn >> 3) * 256 + lane;  // + nt*256 + ks*32

    float acc[2][4][4];
    #pragma unroll
    for (int a = 0; a < 2; a++)
        #pragma unroll
        for (int b2 = 0; b2 < 4; b2++)
            #pragma unroll
            for (int c = 0; c < 4; c++) acc[a][b2][c] = 0.f;

    #pragma unroll
    for (int ks = 0; ks < 8; ks++) {
        unsigned ahi[2][4], alo[2][4];
        #pragma unroll
        for (int mt = 0; mt < 2; mt++) {
            unsigned addr = aAddr + mt * (16 * A_STRIDE) + ks * 32;
            LDSM4(ahi[mt], addr);
            LDSM4(alo[mt], addr + (unsigned)SM_A_LO);
        }
        #pragma unroll
        for (int nt = 0; nt < 4; nt++) {
            uint4 f = wf[nt * 256 + ks * 32];
            #pragma unroll
            for (int mt = 0; mt < 2; mt++) {
                MMA16816(acc[mt][nt], ahi[mt], f.x, f.y);
                MMA16816(acc[mt][nt], ahi[mt], f.z, f.w);
                MMA16816(acc[mt][nt], alo[mt], f.x, f.y);
            }
        }
    }

    // ---- epilogue ----
    #pragma unroll
    for (int mt = 0; mt < 2; mt++) {
        int r0 = row0 + wm + mt * 16 + g;
        #pragma unroll
        for (int nt = 0; nt < 4; nt++) {
            int col = wn + nt * 8 + 2 * t;
            if (r0 < N_NODES)
                *(float2*)(out + r0 * D + col) = make_float2(acc[mt][nt][0], acc[mt][nt][1]);
            if (r0 + 8 < N_NODES)
                *(float2*)(out + (r0 + 8) * D + col) = make_float2(acc[mt][nt][2], acc[mt][nt][3]);
        }
    }
}

// ============================================================================
// K5: per-dst softmax-weighted gather-sum (2x unrolled for MLP)
// ============================================================================
__global__ void k_aggregate(const float* __restrict__ h, float* __restrict__ out) {
    int lane = threadIdx.x & 31;
    int n = blockIdx.x * 8 + (threadIdx.x >> 5);
    if (n >= N_NODES) return;
    int beg = g_off[n], end = g_off[n + 1];
    if (beg == end) return;

    float4 acc = {0.f, 0.f, 0.f, 0.f};
    float den = 0.f;
    int j = beg;
    for (; j + 2 <= end; j += 2) {
        uint2 e0 = g_edge[j], e1 = g_edge[j + 1];
        float4 h0 = ((const float4*)h)[e0.y * 32 + lane];
        float4 h1 = ((const float4*)h)[e1.y * 32 + lane];
        float x0 = __uint_as_float(e0.x), x1 = __uint_as_float(e1.x);
        den += x0 + x1;
        acc.x += x0 * h0.x + x1 * h1.x;
        acc.y += x0 * h0.y + x1 * h1.y;
        acc.z += x0 * h0.z + x1 * h1.z;
        acc.w += x0 * h0.w + x1 * h1.w;
    }
    if (j < end) {
        uint2 e0 = g_edge[j];
        float4 h0 = ((const float4*)h)[e0.y * 32 + lane];
        float x0 = __uint_as_float(e0.x);
        den += x0;
        acc.x += x0 * h0.x; acc.y += x0 * h0.y;
        acc.z += x0 * h0.z; acc.w += x0 * h0.w;
    }
    float inv = 1.f / den;
    float4* op = (float4*)out + n * 32 + lane;
    float4 o = *op;
    o.x += acc.x * inv; o.y += acc.y * inv;
    o.z += acc.z * inv; o.w += acc.w * inv;
    *op = o;
}

// ---------------- launch ----------------
extern "C" void kernel_launch(void* const* d_in, const int* in_sizes, int n_in,
                              void* d_out, int out_size) {
    const float* h          = (const float*)d_in[0];
    const float* emb_rel    = (const float*)d_in[1];
    const float* attn_fc_w  = (const float*)d_in[2];
    const float* attn_fc2_w = (const float*)d_in[3];
    const float* loop_w     = (const float*)d_in[4];
    const int*   esrc       = (const int*)d_in[5];
    const int*   edst       = (const int*)d_in[6];
    const int*   etype      = (const int*)d_in[7];
    float* out = (float*)d_out;

    cudaFuncSetAttribute(k_gemm_hmma, cudaFuncAttributeMaxDynamicSharedMemorySize, GEMM_SMEM);

    k_scores_count<<<SCORE_BLOCKS + COUNT_BLOCKS + WSPLIT_BLOCKS, 256>>>(
        h, emb_rel, attn_fc_w, attn_fc2_w, edst, loop_w);
    k_scan<<<SCAN_BLOCKS, 1024>>>();
    k_fill<<<COUNT_BLOCKS, 256>>>(esrc, edst, etype);
    k_gemm_hmma<<<(N_NODES + 63) / 64, 256, GEMM_SMEM>>>(h, out);
    k_aggregate<<<(N_NODES + 7) / 8, 256>>>(h, out);
}